// round 13
// baseline (speedup 1.0000x reference)
#include <cuda_runtime.h>

// Problem constants (fixed by the dataset)
#define INDIM 256
#define HID   128     // H * F1
#define NH    4
#define FD    32
#define C2    40      // classes
#define NMAXN 100000
#define EMAXE 1600000

// -------- scratch (static device globals; no allocations anywhere) --------
__device__ float g_h1  [(size_t)NMAXN * HID];
__device__ float g_out1[(size_t)NMAXN * HID];
__device__ float g_h2  [(size_t)NMAXN * C2];
__device__ float g_el1 [NMAXN * NH];
__device__ float g_er1 [NMAXN * NH];
__device__ float g_el2 [NMAXN];
__device__ float g_er2 [NMAXN];
__device__ float g_e1  [(size_t)EMAXE * NH];    // slow-path scratch only
__device__ float g_e2  [EMAXE];                 // slow-path scratch only
// CSR by dst
__device__ int   g_deg [NMAXN];
__device__ int   g_off [NMAXN + 1];
__device__ int   g_cur [NMAXN];
__device__ int   g_part[256];
__device__ int   g_csr_src[EMAXE];

// -------- helpers --------
__device__ __forceinline__ float lrelu(float v) { return v > 0.f ? v : 0.2f * v; }
__device__ __forceinline__ float elu(float v)   { return v > 0.f ? v : (__expf(v) - 1.f); }

__device__ __forceinline__ unsigned int f2tf32(float f) {
    unsigned int u; asm("cvt.rna.tf32.f32 %0, %1;" : "=r"(u) : "f"(f)); return u;
}

#define MMA_TF32(d, a, b) \
    asm volatile("mma.sync.aligned.m16n8k8.row.col.f32.tf32.tf32.f32 " \
        "{%0,%1,%2,%3}, {%4,%5,%6,%7}, {%8,%9}, {%0,%1,%2,%3};" \
        : "+f"((d)[0]), "+f"((d)[1]), "+f"((d)[2]), "+f"((d)[3]) \
        : "r"((a)[0]), "r"((a)[1]), "r"((a)[2]), "r"((a)[3]), \
          "r"((b)[0]), "r"((b)[1]))

// ============================================================================
// GEMM1 (TF32) + fused elr1 — packed-pair smem fragments (LDS.64 loads).
// Layout: element k maps to slot j = (k>>3)*8 + (k&3)*2 + ((k>>2)&1), so
// (k, k+4) sit adjacently and one 8B load fetches a fragment k-pair.
// Row stride 40 words (20 8B-units, ≡4 mod 16) => conflict-free LDS.64.
// ============================================================================
__global__ __launch_bounds__(256)
void gemm1_tc(const float* __restrict__ A, const float* __restrict__ W,
              float* __restrict__ C,
              const float* __restrict__ al, const float* __restrict__ ar,
              int nrows)
{
    __shared__ unsigned int As2[128][40];  // [row][packed j]
    __shared__ unsigned int Wt2[128][40];  // [col][packed j]  (transposed W)
    __shared__ float sel[128][4], ser[128][4];

    const int tid  = threadIdx.x;
    const int wid  = tid >> 5;
    const int lane = tid & 31;
    const int wr   = wid >> 1;
    const int wc   = wid & 1;
    const int r0   = blockIdx.x * 128;
    const int qr   = lane >> 2;
    const int qc   = lane & 3;

    float acc[2][8][4];
#pragma unroll
    for (int mt = 0; mt < 2; mt++)
#pragma unroll
        for (int nt = 0; nt < 8; nt++)
#pragma unroll
            for (int j = 0; j < 4; j++) acc[mt][nt][j] = 0.f;

    for (int kt = 0; kt < INDIM; kt += 32) {
        // A tile: 128x32, packed pairs
#pragma unroll
        for (int i = 0; i < 4; i++) {
            int idx = tid + i * 256;
            int row = idx >> 3;
            int q   = (idx & 7) * 4;            // q = 4m
            float4 v = make_float4(0.f, 0.f, 0.f, 0.f);
            if (r0 + row < nrows)
                v = *(const float4*)(A + (size_t)(r0 + row) * INDIM + kt + q);
            int m = q >> 2;
            int base = (m >> 1) * 8 + (m & 1);
            As2[row][base + 0] = f2tf32(v.x);
            As2[row][base + 2] = f2tf32(v.y);
            As2[row][base + 4] = f2tf32(v.z);
            As2[row][base + 6] = f2tf32(v.w);
        }
        // W tile: 32x128, transposed + packed (col per thread-group; coalesced)
#pragma unroll
        for (int i = 0; i < 4; i++) {
            int idx = tid + i * 256;
            int col = idx & 127;
            int kg  = idx >> 7;                 // 0..7 => k = kg*4 + t
            int jb  = (kg >> 1) * 8 + (kg & 1);
#pragma unroll
            for (int t = 0; t < 4; t++) {
                float v = W[(size_t)(kt + kg * 4 + t) * 128 + col];
                Wt2[col][jb + 2 * t] = f2tf32(v);
            }
        }
        __syncthreads();

#pragma unroll
        for (int kc = 0; kc < 4; kc++) {
            const int jq = kc * 8 + qc * 2;
            unsigned int a[2][4], b[8][2];
#pragma unroll
            for (int mt = 0; mt < 2; mt++) {
                int row = wr * 32 + mt * 16 + qr;
                uint2 p0 = *(const uint2*)(&As2[row    ][jq]);
                uint2 p1 = *(const uint2*)(&As2[row + 8][jq]);
                a[mt][0] = p0.x; a[mt][1] = p1.x;
                a[mt][2] = p0.y; a[mt][3] = p1.y;
            }
#pragma unroll
            for (int nt = 0; nt < 8; nt++) {
                int col = wc * 64 + nt * 8 + qr;
                uint2 pb = *(const uint2*)(&Wt2[col][jq]);
                b[nt][0] = pb.x; b[nt][1] = pb.y;
            }
#pragma unroll
            for (int mt = 0; mt < 2; mt++)
#pragma unroll
                for (int nt = 0; nt < 8; nt++)
                    MMA_TF32(acc[mt][nt], a[mt], b[nt]);
        }
        __syncthreads();
    }

    if (tid < 128) {
        *(float4*)(&sel[tid][0]) = make_float4(0.f, 0.f, 0.f, 0.f);
        *(float4*)(&ser[tid][0]) = make_float4(0.f, 0.f, 0.f, 0.f);
    }
    __syncthreads();

#pragma unroll
    for (int mt = 0; mt < 2; mt++) {
#pragma unroll
        for (int half = 0; half < 2; half++) {
            int lrow = wr * 32 + mt * 16 + qr + half * 8;
            int grow = r0 + lrow;
            bool ok = grow < nrows;
            float pel[2] = {0.f, 0.f}, per[2] = {0.f, 0.f};
#pragma unroll
            for (int nt = 0; nt < 8; nt++) {
                float v0 = acc[mt][nt][half * 2 + 0];
                float v1 = acc[mt][nt][half * 2 + 1];
                int col0 = wc * 64 + nt * 8 + qc * 2;
                if (ok)
                    *(float2*)(C + (size_t)grow * 128 + col0) = make_float2(v0, v1);
                int h = nt >> 2;
                pel[h] += v0 * al[col0] + v1 * al[col0 + 1];
                per[h] += v0 * ar[col0] + v1 * ar[col0 + 1];
            }
            atomicAdd(&sel[lrow][2 * wc + 0], pel[0]);
            atomicAdd(&sel[lrow][2 * wc + 1], pel[1]);
            atomicAdd(&ser[lrow][2 * wc + 0], per[0]);
            atomicAdd(&ser[lrow][2 * wc + 1], per[1]);
        }
    }
    __syncthreads();

    if (tid < 128 && r0 + tid < nrows) {
        *(float4*)(g_el1 + (size_t)(r0 + tid) * 4) = *(float4*)(&sel[tid][0]);
        *(float4*)(g_er1 + (size_t)(r0 + tid) * 4) = *(float4*)(&ser[tid][0]);
    }
}

// ============================================================================
// GEMM2 (TF32) + fused elr2 — unchanged from R12 (validated)
// ============================================================================
__global__ __launch_bounds__(256)
void gemm2_tc(const float* __restrict__ A, const float* __restrict__ W2,
              float* __restrict__ C,
              const float* __restrict__ al, const float* __restrict__ ar,
              int nrows)
{
    __shared__ unsigned int As[128][36];
    __shared__ unsigned int Ws[32][72];
    __shared__ float sel[128], ser[128];

    const int tid  = threadIdx.x;
    const int wid  = tid >> 5;
    const int lane = tid & 31;
    const int wr   = wid >> 1;
    const int wc   = wid & 1;
    const int r0   = blockIdx.x * 128;
    const int qr   = lane >> 2;
    const int qc   = lane & 3;

    float acc[2][4][4];
#pragma unroll
    for (int mt = 0; mt < 2; mt++)
#pragma unroll
        for (int nt = 0; nt < 4; nt++)
#pragma unroll
            for (int j = 0; j < 4; j++) acc[mt][nt][j] = 0.f;

    for (int kt = 0; kt < HID; kt += 32) {
#pragma unroll
        for (int i = 0; i < 4; i++) {
            int idx = tid + i * 256;
            int row = idx >> 3;
            int q   = (idx & 7) * 4;
            float4 v = make_float4(0.f, 0.f, 0.f, 0.f);
            if (r0 + row < nrows)
                v = *(const float4*)(A + (size_t)(r0 + row) * HID + kt + q);
            As[row][q + 0] = f2tf32(v.x); As[row][q + 1] = f2tf32(v.y);
            As[row][q + 2] = f2tf32(v.z); As[row][q + 3] = f2tf32(v.w);
        }
#pragma unroll
        for (int i = 0; i < 2; i++) {
            int idx = tid + i * 256;
            int kr  = idx >> 4;
            int cq  = (idx & 15) * 4;
            float4 v = make_float4(0.f, 0.f, 0.f, 0.f);
            if (cq < C2)
                v = *(const float4*)(W2 + (size_t)(kt + kr) * C2 + cq);
            Ws[kr][cq + 0] = f2tf32(v.x); Ws[kr][cq + 1] = f2tf32(v.y);
            Ws[kr][cq + 2] = f2tf32(v.z); Ws[kr][cq + 3] = f2tf32(v.w);
        }
        __syncthreads();

#pragma unroll
        for (int kc = 0; kc < 4; kc++) {
            const int k0 = kc * 8;
            unsigned int a[2][4], b[4][2];
#pragma unroll
            for (int mt = 0; mt < 2; mt++) {
                int row = wr * 32 + mt * 16 + qr;
                a[mt][0] = As[row    ][k0 + qc];
                a[mt][1] = As[row + 8][k0 + qc];
                a[mt][2] = As[row    ][k0 + qc + 4];
                a[mt][3] = As[row + 8][k0 + qc + 4];
            }
#pragma unroll
            for (int nt = 0; nt < 4; nt++) {
                int col = wc * 32 + nt * 8 + qr;
                b[nt][0] = Ws[k0 + qc    ][col];
                b[nt][1] = Ws[k0 + qc + 4][col];
            }
#pragma unroll
            for (int mt = 0; mt < 2; mt++)
#pragma unroll
                for (int nt = 0; nt < 4; nt++)
                    MMA_TF32(acc[mt][nt], a[mt], b[nt]);
        }
        __syncthreads();
    }

    if (tid < 128) { sel[tid] = 0.f; ser[tid] = 0.f; }
    __syncthreads();

#pragma unroll
    for (int mt = 0; mt < 2; mt++) {
#pragma unroll
        for (int half = 0; half < 2; half++) {
            int lrow = wr * 32 + mt * 16 + qr + half * 8;
            int grow = r0 + lrow;
            bool ok = grow < nrows;
            float pel = 0.f, per = 0.f;
#pragma unroll
            for (int nt = 0; nt < 4; nt++) {
                float v0 = acc[mt][nt][half * 2 + 0];
                float v1 = acc[mt][nt][half * 2 + 1];
                int col0 = wc * 32 + nt * 8 + qc * 2;
                if (col0 < C2) {
                    if (ok)
                        *(float2*)(C + (size_t)grow * C2 + col0) = make_float2(v0, v1);
                    pel += v0 * al[col0] + v1 * al[col0 + 1];
                    per += v0 * ar[col0] + v1 * ar[col0 + 1];
                }
            }
            atomicAdd(&sel[lrow], pel);
            atomicAdd(&ser[lrow], per);
        }
    }
    __syncthreads();

    if (tid < 128 && r0 + tid < nrows) {
        g_el2[r0 + tid] = sel[tid];
        g_er2[r0 + tid] = ser[tid];
    }
}

// ============================================================================
// CSR build
// ============================================================================
__global__ void zero_deg(int n)
{
    int i = blockIdx.x * blockDim.x + threadIdx.x;
    if (i < n) g_deg[i] = 0;
}

__global__ void count_kernel(const int* __restrict__ dst, int e)
{
    int i = blockIdx.x * blockDim.x + threadIdx.x;
    if (i < e) atomicAdd(&g_deg[dst[i]], 1);
}

__global__ __launch_bounds__(1024)
void scan_local(int n)
{
    __shared__ int sh[1024];
    int t = threadIdx.x;
    int i = blockIdx.x * 1024 + t;
    int val = (i < n) ? g_deg[i] : 0;
    sh[t] = val;
    __syncthreads();
#pragma unroll
    for (int d = 1; d < 1024; d <<= 1) {
        int x = (t >= d) ? sh[t - d] : 0;
        __syncthreads();
        sh[t] += x;
        __syncthreads();
    }
    if (i < n) g_off[i] = sh[t] - val;
    if (t == 1023) g_part[blockIdx.x] = sh[1023];
}

__global__ void scan_part(int nblk, int n)
{
    if (threadIdx.x != 0 || blockIdx.x != 0) return;
    int run = 0;
    for (int b = 0; b < nblk; b++) {
        int v = g_part[b];
        g_part[b] = run;
        run += v;
    }
    g_off[n] = run;
}

__global__ void add_part(int n)
{
    int i = blockIdx.x * blockDim.x + threadIdx.x;
    if (i >= n) return;
    int o = g_off[i] + g_part[i >> 10];
    g_off[i] = o;
    g_cur[i] = o;
}

__global__ void scatter_kernel(const int* __restrict__ src, const int* __restrict__ dst, int e)
{
    int i = blockIdx.x * blockDim.x + threadIdx.x;
    if (i >= e) return;
    int d = dst[i];
    int pos = atomicAdd(&g_cur[d], 1);
    g_csr_src[pos] = src[i];
}

// ============================================================================
// Layer 1: warp per node — register softmax (no max pass), simple gather
// ============================================================================
__global__ __launch_bounds__(256)
void gat1_kernel(const float* __restrict__ b1, int n)
{
    __shared__ float s_alpha[8][32][4];
    __shared__ int   s_src[8][32];

    int w    = threadIdx.x >> 5;
    int node = (blockIdx.x * blockDim.x + threadIdx.x) >> 5;
    int lane = threadIdx.x & 31;
    if (node >= n) return;

    int off = g_off[node];
    int deg = g_off[node + 1] - off;
    int head = lane >> 3;

    float4 erd = *(const float4*)(g_er1 + (size_t)node * 4);
    float4 acc = make_float4(0.f, 0.f, 0.f, 0.f);

    if (deg <= 32) {
        bool valid = lane < deg;
        int s = 0;
        float4 ee = make_float4(0.f, 0.f, 0.f, 0.f);
        if (valid) {
            s = g_csr_src[off + lane];
            float4 a = *(const float4*)(g_el1 + (size_t)s * 4);
            ee.x = __expf(lrelu(a.x + erd.x));
            ee.y = __expf(lrelu(a.y + erd.y));
            ee.z = __expf(lrelu(a.z + erd.z));
            ee.w = __expf(lrelu(a.w + erd.w));
        }
        float4 sm = ee;
#pragma unroll
        for (int o = 16; o; o >>= 1) {
            sm.x += __shfl_xor_sync(0xffffffffu, sm.x, o);
            sm.y += __shfl_xor_sync(0xffffffffu, sm.y, o);
            sm.z += __shfl_xor_sync(0xffffffffu, sm.z, o);
            sm.w += __shfl_xor_sync(0xffffffffu, sm.w, o);
        }
        float4 al4 = make_float4(0.f, 0.f, 0.f, 0.f);
        if (valid) {
            al4.x = ee.x / sm.x; al4.y = ee.y / sm.y;
            al4.z = ee.z / sm.z; al4.w = ee.w / sm.w;
        }
        s_src[w][lane] = s;
        *(float4*)(&s_alpha[w][lane][0]) = al4;
        __syncwarp();

        for (int q = 0; q < deg; q++) {
            int   sq = s_src[w][q];
            float a  = s_alpha[w][q][head];
            float4 hv = *(const float4*)(g_h1 + (size_t)sq * HID + lane * 4);
            acc.x += a * hv.x; acc.y += a * hv.y;
            acc.z += a * hv.z; acc.w += a * hv.w;
        }
    } else {
        float4 sm = make_float4(0.f, 0.f, 0.f, 0.f);
        for (int base = 0; base < deg; base += 32) {
            int j = base + lane;
            if (j < deg) {
                int s = g_csr_src[off + j];
                float4 a = *(const float4*)(g_el1 + (size_t)s * 4);
                float4 e4;
                e4.x = __expf(lrelu(a.x + erd.x));
                e4.y = __expf(lrelu(a.y + erd.y));
                e4.z = __expf(lrelu(a.z + erd.z));
                e4.w = __expf(lrelu(a.w + erd.w));
                *(float4*)(g_e1 + (size_t)(off + j) * 4) = e4;
                sm.x += e4.x; sm.y += e4.y; sm.z += e4.z; sm.w += e4.w;
            }
        }
#pragma unroll
        for (int o = 16; o; o >>= 1) {
            sm.x += __shfl_xor_sync(0xffffffffu, sm.x, o);
            sm.y += __shfl_xor_sync(0xffffffffu, sm.y, o);
            sm.z += __shfl_xor_sync(0xffffffffu, sm.z, o);
            sm.w += __shfl_xor_sync(0xffffffffu, sm.w, o);
        }
        float invh = 1.f / ((head == 0) ? sm.x : (head == 1) ? sm.y : (head == 2) ? sm.z : sm.w);

        for (int base = 0; base < deg; base += 32) {
            int cnt = min(32, deg - base);
            int j = base + lane;
            int s = 0;
            float4 ee = make_float4(0.f, 0.f, 0.f, 0.f);
            if (j < deg) {
                s = g_csr_src[off + j];
                ee = *(const float4*)(g_e1 + (size_t)(off + j) * 4);
            }
            s_src[w][lane] = s;
            *(float4*)(&s_alpha[w][lane][0]) = ee;
            __syncwarp();
            for (int q = 0; q < cnt; q++) {
                int   sq = s_src[w][q];
                float a  = s_alpha[w][q][head] * invh;
                float4 hv = *(const float4*)(g_h1 + (size_t)sq * HID + lane * 4);
                acc.x += a * hv.x; acc.y += a * hv.y;
                acc.z += a * hv.z; acc.w += a * hv.w;
            }
            __syncwarp();
        }
    }

    float4 bb = *(const float4*)(b1 + lane * 4);
    float4 o;
    o.x = elu(acc.x + bb.x); o.y = elu(acc.y + bb.y);
    o.z = elu(acc.z + bb.z); o.w = elu(acc.w + bb.w);
    *(float4*)(g_out1 + (size_t)node * HID + lane * 4) = o;
}

// ============================================================================
// Layer 2: warp per node (1 head, C=40); no max pass; simple gather
// ============================================================================
__global__ __launch_bounds__(256)
void gat2_kernel(float* __restrict__ out, const float* __restrict__ b2, int n)
{
    __shared__ float s_a[8][32];
    __shared__ int   s_src[8][32];

    int w    = threadIdx.x >> 5;
    int node = (blockIdx.x * blockDim.x + threadIdx.x) >> 5;
    int lane = threadIdx.x & 31;
    if (node >= n) return;

    int off = g_off[node];
    int deg = g_off[node + 1] - off;
    float erd = g_er2[node];

    float acc0 = 0.f, acc1 = 0.f;

    if (deg <= 32) {
        bool valid = lane < deg;
        int s = 0;
        float ee = 0.f;
        if (valid) {
            s = g_csr_src[off + lane];
            ee = __expf(lrelu(g_el2[s] + erd));
        }
        float sm = ee;
#pragma unroll
        for (int o = 16; o; o >>= 1)
            sm += __shfl_xor_sync(0xffffffffu, sm, o);
        float alpha = valid ? (ee / sm) : 0.f;

        s_src[w][lane] = s;
        s_a[w][lane] = alpha;
        __syncwarp();

        for (int q = 0; q < deg; q++) {
            int   sq = s_src[w][q];
            float a  = s_a[w][q];
            const float* hp = g_h2 + (size_t)sq * C2;
            acc0 += a * hp[lane];
            if (lane < 8) acc1 += a * hp[32 + lane];
        }
    } else {
        float sm = 0.f;
        for (int base = 0; base < deg; base += 32) {
            int j = base + lane;
            if (j < deg) {
                int s = g_csr_src[off + j];
                float ee = __expf(lrelu(g_el2[s] + erd));
                g_e2[off + j] = ee;
                sm += ee;
            }
        }
#pragma unroll
        for (int o = 16; o; o >>= 1)
            sm += __shfl_xor_sync(0xffffffffu, sm, o);
        float inv = 1.f / sm;

        for (int base = 0; base < deg; base += 32) {
            int cnt = min(32, deg - base);
            int j = base + lane;
            int s = 0; float ee = 0.f;
            if (j < deg) {
                s = g_csr_src[off + j];
                ee = g_e2[off + j];
            }
            s_src[w][lane] = s;
            s_a[w][lane] = ee * inv;
            __syncwarp();
            for (int q = 0; q < cnt; q++) {
                int   sq = s_src[w][q];
                float a  = s_a[w][q];
                const float* hp = g_h2 + (size_t)sq * C2;
                acc0 += a * hp[lane];
                if (lane < 8) acc1 += a * hp[32 + lane];
            }
            __syncwarp();
        }
    }

    out[(size_t)node * C2 + lane] = acc0 + b2[lane];
    if (lane < 8)
        out[(size_t)node * C2 + 32 + lane] = acc1 + b2[32 + lane];
}

// ============================================================================
// launch — CSR ∥ gemm1 fork (gemm1 = submission #4, ncu target), then serial
// ============================================================================
extern "C" void kernel_launch(void* const* d_in, const int* in_sizes, int n_in,
                              void* d_out, int out_size)
{
    const float* feat = (const float*)d_in[0];
    const int*   src  = (const int*)  d_in[1];
    const int*   dst  = (const int*)  d_in[2];
    const float* W1   = (const float*)d_in[3];
    const float* al1  = (const float*)d_in[4];
    const float* ar1  = (const float*)d_in[5];
    const float* b1   = (const float*)d_in[6];
    const float* W2   = (const float*)d_in[7];
    const float* al2  = (const float*)d_in[8];
    const float* ar2  = (const float*)d_in[9];
    const float* b2   = (const float*)d_in[10];
    float* out = (float*)d_out;

    const int n = in_sizes[0] / INDIM;   // 100000
    const int e = in_sizes[1];           // 1600000

    float *p_h1 = 0, *p_out1 = 0, *p_h2 = 0;
    cudaGetSymbolAddress((void**)&p_h1,   g_h1);
    cudaGetSymbolAddress((void**)&p_out1, g_out1);
    cudaGetSymbolAddress((void**)&p_h2,   g_h2);

    static cudaStream_t s2 = 0;
    static cudaEvent_t ev_fork = 0, ev_join = 0;
    if (!s2) {
        cudaStreamCreateWithFlags(&s2, cudaStreamNonBlocking);
        cudaEventCreateWithFlags(&ev_fork, cudaEventDisableTiming);
        cudaEventCreateWithFlags(&ev_join, cudaEventDisableTiming);
    }

    const int TB = 256;
    const int nblk_scan = (n + 1023) / 1024;

    // fork
    cudaEventRecord(ev_fork, 0);
    cudaStreamWaitEvent(s2, ev_fork, 0);

    // s2: first 3 CSR kernels (#1-3)
    zero_deg<<<(n + TB - 1) / TB, TB, 0, s2>>>(n);
    count_kernel<<<(e + TB - 1) / TB, TB, 0, s2>>>(dst, e);
    scan_local<<<nblk_scan, 1024, 0, s2>>>(n);

    // stream 0: gemm1 TF32 (#4 — ncu target)
    gemm1_tc<<<(n + 127) / 128, 256>>>(feat, W1, p_h1, al1, ar1, n);

    // s2: rest of CSR
    scan_part<<<1, 32, 0, s2>>>(nblk_scan, n);
    add_part<<<(n + TB - 1) / TB, TB, 0, s2>>>(n);
    scatter_kernel<<<(e + TB - 1) / TB, TB, 0, s2>>>(src, dst, e);
    cudaEventRecord(ev_join, s2);

    // join, then serial: gat1 -> gemm2 (TF32) -> gat2
    cudaStreamWaitEvent(0, ev_join, 0);
    gat1_kernel<<<(n * 32 + TB - 1) / TB, TB>>>(b1, n);
    gemm2_tc<<<(n + 127) / 128, 256>>>(p_out1, W2, p_h2, al2, ar2, n);
    gat2_kernel<<<(n * 32 + TB - 1) / TB, TB>>>(out, b2, n);
}

// round 15
// speedup vs baseline: 1.1410x; 1.1410x over previous
#include <cuda_runtime.h>
#include <cuda_fp16.h>

// Problem constants (fixed by the dataset)
#define INDIM 256
#define HID   128     // H * F1
#define NH    4
#define FD    32
#define C2    40      // classes
#define NMAXN 100000
#define EMAXE 1600000

// -------- scratch (static device globals; no allocations anywhere) --------
__device__ __half g_h1h[(size_t)NMAXN * HID];   // layer1 projection (fp16)
__device__ float g_out1[(size_t)NMAXN * HID];
__device__ float g_h2  [(size_t)NMAXN * C2];
__device__ float g_el1 [NMAXN * NH];
__device__ float g_er1 [NMAXN * NH];
__device__ float g_el2 [NMAXN];
__device__ float g_er2 [NMAXN];
__device__ float g_e1  [(size_t)EMAXE * NH];    // slow-path scratch only
__device__ float g_e2  [EMAXE];                 // slow-path scratch only
// CSR by dst
__device__ int   g_deg [NMAXN];
__device__ int   g_off [NMAXN + 1];
__device__ int   g_cur [NMAXN];
__device__ int   g_part[256];
__device__ int   g_csr_src[EMAXE];

// -------- helpers --------
__device__ __forceinline__ float lrelu(float v) { return v > 0.f ? v : 0.2f * v; }
__device__ __forceinline__ float elu(float v)   { return v > 0.f ? v : (__expf(v) - 1.f); }

__device__ __forceinline__ unsigned int f2tf32(float f) {
    unsigned int u; asm("cvt.rna.tf32.f32 %0, %1;" : "=r"(u) : "f"(f)); return u;
}

#define MMA_TF32(d, a, b) \
    asm volatile("mma.sync.aligned.m16n8k8.row.col.f32.tf32.tf32.f32 " \
        "{%0,%1,%2,%3}, {%4,%5,%6,%7}, {%8,%9}, {%0,%1,%2,%3};" \
        : "+f"((d)[0]), "+f"((d)[1]), "+f"((d)[2]), "+f"((d)[3]) \
        : "r"((a)[0]), "r"((a)[1]), "r"((a)[2]), "r"((a)[3]), \
          "r"((b)[0]), "r"((b)[1]))

// ============================================================================
// GEMM1 (TF32) + fused elr1 — R12-validated structure; h1 stored as fp16.
// Block 128x128, K=256, BK=32. 8 warps 4x2; warp = 32x64 = 2x8 m16n8k8.
// ============================================================================
__global__ __launch_bounds__(256)
void gemm1_tc(const float* __restrict__ A, const float* __restrict__ W,
              __half* __restrict__ H,
              const float* __restrict__ al, const float* __restrict__ ar,
              int nrows)
{
    __shared__ unsigned int As[128][36];   // [row][k]
    __shared__ unsigned int Ws[32][136];   // [k][col]
    __shared__ float sel[128][4], ser[128][4];

    const int tid  = threadIdx.x;
    const int wid  = tid >> 5;
    const int lane = tid & 31;
    const int wr   = wid >> 1;
    const int wc   = wid & 1;
    const int r0   = blockIdx.x * 128;
    const int qr   = lane >> 2;
    const int qc   = lane & 3;

    float acc[2][8][4];
#pragma unroll
    for (int mt = 0; mt < 2; mt++)
#pragma unroll
        for (int nt = 0; nt < 8; nt++)
#pragma unroll
            for (int j = 0; j < 4; j++) acc[mt][nt][j] = 0.f;

    for (int kt = 0; kt < INDIM; kt += 32) {
#pragma unroll
        for (int i = 0; i < 4; i++) {
            int idx = tid + i * 256;
            int row = idx >> 3;
            int q   = (idx & 7) * 4;
            float4 v = make_float4(0.f, 0.f, 0.f, 0.f);
            if (r0 + row < nrows)
                v = *(const float4*)(A + (size_t)(r0 + row) * INDIM + kt + q);
            As[row][q + 0] = f2tf32(v.x); As[row][q + 1] = f2tf32(v.y);
            As[row][q + 2] = f2tf32(v.z); As[row][q + 3] = f2tf32(v.w);
        }
#pragma unroll
        for (int i = 0; i < 4; i++) {
            int idx = tid + i * 256;
            int kr  = idx >> 5;
            int cq  = (idx & 31) * 4;
            float4 v = *(const float4*)(W + (size_t)(kt + kr) * 128 + cq);
            Ws[kr][cq + 0] = f2tf32(v.x); Ws[kr][cq + 1] = f2tf32(v.y);
            Ws[kr][cq + 2] = f2tf32(v.z); Ws[kr][cq + 3] = f2tf32(v.w);
        }
        __syncthreads();

#pragma unroll
        for (int kc = 0; kc < 4; kc++) {
            const int k0 = kc * 8;
            unsigned int a[2][4], b[8][2];
#pragma unroll
            for (int mt = 0; mt < 2; mt++) {
                int row = wr * 32 + mt * 16 + qr;
                a[mt][0] = As[row    ][k0 + qc];
                a[mt][1] = As[row + 8][k0 + qc];
                a[mt][2] = As[row    ][k0 + qc + 4];
                a[mt][3] = As[row + 8][k0 + qc + 4];
            }
#pragma unroll
            for (int nt = 0; nt < 8; nt++) {
                int col = wc * 64 + nt * 8 + qr;
                b[nt][0] = Ws[k0 + qc    ][col];
                b[nt][1] = Ws[k0 + qc + 4][col];
            }
#pragma unroll
            for (int mt = 0; mt < 2; mt++)
#pragma unroll
                for (int nt = 0; nt < 8; nt++)
                    MMA_TF32(acc[mt][nt], a[mt], b[nt]);
        }
        __syncthreads();
    }

    if (tid < 128) {
        *(float4*)(&sel[tid][0]) = make_float4(0.f, 0.f, 0.f, 0.f);
        *(float4*)(&ser[tid][0]) = make_float4(0.f, 0.f, 0.f, 0.f);
    }
    __syncthreads();

#pragma unroll
    for (int mt = 0; mt < 2; mt++) {
#pragma unroll
        for (int half = 0; half < 2; half++) {
            int lrow = wr * 32 + mt * 16 + qr + half * 8;
            int grow = r0 + lrow;
            bool ok = grow < nrows;
            float pel[2] = {0.f, 0.f}, per[2] = {0.f, 0.f};
#pragma unroll
            for (int nt = 0; nt < 8; nt++) {
                float v0 = acc[mt][nt][half * 2 + 0];
                float v1 = acc[mt][nt][half * 2 + 1];
                int col0 = wc * 64 + nt * 8 + qc * 2;
                if (ok) {
                    __half2 p = __floats2half2_rn(v0, v1);
                    *(__half2*)(H + (size_t)grow * 128 + col0) = p;
                }
                int h = nt >> 2;
                pel[h] += v0 * al[col0] + v1 * al[col0 + 1];
                per[h] += v0 * ar[col0] + v1 * ar[col0 + 1];
            }
            atomicAdd(&sel[lrow][2 * wc + 0], pel[0]);
            atomicAdd(&sel[lrow][2 * wc + 1], pel[1]);
            atomicAdd(&ser[lrow][2 * wc + 0], per[0]);
            atomicAdd(&ser[lrow][2 * wc + 1], per[1]);
        }
    }
    __syncthreads();

    if (tid < 128 && r0 + tid < nrows) {
        *(float4*)(g_el1 + (size_t)(r0 + tid) * 4) = *(float4*)(&sel[tid][0]);
        *(float4*)(g_er1 + (size_t)(r0 + tid) * 4) = *(float4*)(&ser[tid][0]);
    }
}

// ============================================================================
// GEMM2 (TF32) + fused elr2 — R12-validated, unchanged
// ============================================================================
__global__ __launch_bounds__(256)
void gemm2_tc(const float* __restrict__ A, const float* __restrict__ W2,
              float* __restrict__ C,
              const float* __restrict__ al, const float* __restrict__ ar,
              int nrows)
{
    __shared__ unsigned int As[128][36];
    __shared__ unsigned int Ws[32][72];
    __shared__ float sel[128], ser[128];

    const int tid  = threadIdx.x;
    const int wid  = tid >> 5;
    const int lane = tid & 31;
    const int wr   = wid >> 1;
    const int wc   = wid & 1;
    const int r0   = blockIdx.x * 128;
    const int qr   = lane >> 2;
    const int qc   = lane & 3;

    float acc[2][4][4];
#pragma unroll
    for (int mt = 0; mt < 2; mt++)
#pragma unroll
        for (int nt = 0; nt < 4; nt++)
#pragma unroll
            for (int j = 0; j < 4; j++) acc[mt][nt][j] = 0.f;

    for (int kt = 0; kt < HID; kt += 32) {
#pragma unroll
        for (int i = 0; i < 4; i++) {
            int idx = tid + i * 256;
            int row = idx >> 3;
            int q   = (idx & 7) * 4;
            float4 v = make_float4(0.f, 0.f, 0.f, 0.f);
            if (r0 + row < nrows)
                v = *(const float4*)(A + (size_t)(r0 + row) * HID + kt + q);
            As[row][q + 0] = f2tf32(v.x); As[row][q + 1] = f2tf32(v.y);
            As[row][q + 2] = f2tf32(v.z); As[row][q + 3] = f2tf32(v.w);
        }
#pragma unroll
        for (int i = 0; i < 2; i++) {
            int idx = tid + i * 256;
            int kr  = idx >> 4;
            int cq  = (idx & 15) * 4;
            float4 v = make_float4(0.f, 0.f, 0.f, 0.f);
            if (cq < C2)
                v = *(const float4*)(W2 + (size_t)(kt + kr) * C2 + cq);
            Ws[kr][cq + 0] = f2tf32(v.x); Ws[kr][cq + 1] = f2tf32(v.y);
            Ws[kr][cq + 2] = f2tf32(v.z); Ws[kr][cq + 3] = f2tf32(v.w);
        }
        __syncthreads();

#pragma unroll
        for (int kc = 0; kc < 4; kc++) {
            const int k0 = kc * 8;
            unsigned int a[2][4], b[4][2];
#pragma unroll
            for (int mt = 0; mt < 2; mt++) {
                int row = wr * 32 + mt * 16 + qr;
                a[mt][0] = As[row    ][k0 + qc];
                a[mt][1] = As[row + 8][k0 + qc];
                a[mt][2] = As[row    ][k0 + qc + 4];
                a[mt][3] = As[row + 8][k0 + qc + 4];
            }
#pragma unroll
            for (int nt = 0; nt < 4; nt++) {
                int col = wc * 32 + nt * 8 + qr;
                b[nt][0] = Ws[k0 + qc    ][col];
                b[nt][1] = Ws[k0 + qc + 4][col];
            }
#pragma unroll
            for (int mt = 0; mt < 2; mt++)
#pragma unroll
                for (int nt = 0; nt < 4; nt++)
                    MMA_TF32(acc[mt][nt], a[mt], b[nt]);
        }
        __syncthreads();
    }

    if (tid < 128) { sel[tid] = 0.f; ser[tid] = 0.f; }
    __syncthreads();

#pragma unroll
    for (int mt = 0; mt < 2; mt++) {
#pragma unroll
        for (int half = 0; half < 2; half++) {
            int lrow = wr * 32 + mt * 16 + qr + half * 8;
            int grow = r0 + lrow;
            bool ok = grow < nrows;
            float pel = 0.f, per = 0.f;
#pragma unroll
            for (int nt = 0; nt < 4; nt++) {
                float v0 = acc[mt][nt][half * 2 + 0];
                float v1 = acc[mt][nt][half * 2 + 1];
                int col0 = wc * 32 + nt * 8 + qc * 2;
                if (col0 < C2) {
                    if (ok)
                        *(float2*)(C + (size_t)grow * C2 + col0) = make_float2(v0, v1);
                    pel += v0 * al[col0] + v1 * al[col0 + 1];
                    per += v0 * ar[col0] + v1 * ar[col0 + 1];
                }
            }
            atomicAdd(&sel[lrow], pel);
            atomicAdd(&ser[lrow], per);
        }
    }
    __syncthreads();

    if (tid < 128 && r0 + tid < nrows) {
        g_el2[r0 + tid] = sel[tid];
        g_er2[r0 + tid] = ser[tid];
    }
}

// ============================================================================
// CSR build
// ============================================================================
__global__ void zero_deg(int n)
{
    int i = blockIdx.x * blockDim.x + threadIdx.x;
    if (i < n) g_deg[i] = 0;
}

__global__ void count_kernel(const int* __restrict__ dst, int e)
{
    int i = blockIdx.x * blockDim.x + threadIdx.x;
    if (i < e) atomicAdd(&g_deg[dst[i]], 1);
}

__global__ __launch_bounds__(1024)
void scan_local(int n)
{
    __shared__ int sh[1024];
    int t = threadIdx.x;
    int i = blockIdx.x * 1024 + t;
    int val = (i < n) ? g_deg[i] : 0;
    sh[t] = val;
    __syncthreads();
#pragma unroll
    for (int d = 1; d < 1024; d <<= 1) {
        int x = (t >= d) ? sh[t - d] : 0;
        __syncthreads();
        sh[t] += x;
        __syncthreads();
    }
    if (i < n) g_off[i] = sh[t] - val;
    if (t == 1023) g_part[blockIdx.x] = sh[1023];
}

__global__ void scan_part(int nblk, int n)
{
    if (threadIdx.x != 0 || blockIdx.x != 0) return;
    int run = 0;
    for (int b = 0; b < nblk; b++) {
        int v = g_part[b];
        g_part[b] = run;
        run += v;
    }
    g_off[n] = run;
}

__global__ void add_part(int n)
{
    int i = blockIdx.x * blockDim.x + threadIdx.x;
    if (i >= n) return;
    int o = g_off[i] + g_part[i >> 10];
    g_off[i] = o;
    g_cur[i] = o;
}

__global__ void scatter_kernel(const int* __restrict__ src, const int* __restrict__ dst, int e)
{
    int i = blockIdx.x * blockDim.x + threadIdx.x;
    if (i >= e) return;
    int d = dst[i];
    int pos = atomicAdd(&g_cur[d], 1);
    g_csr_src[pos] = src[i];
}

// ============================================================================
// Layer 1: warp per node — register softmax, gather from fp16 h1
// ============================================================================
__global__ __launch_bounds__(256)
void gat1_kernel(const float* __restrict__ b1, int n)
{
    __shared__ float s_alpha[8][32][4];
    __shared__ int   s_src[8][32];

    int w    = threadIdx.x >> 5;
    int node = (blockIdx.x * blockDim.x + threadIdx.x) >> 5;
    int lane = threadIdx.x & 31;
    if (node >= n) return;

    int off = g_off[node];
    int deg = g_off[node + 1] - off;
    int head = lane >> 3;

    float4 erd = *(const float4*)(g_er1 + (size_t)node * 4);
    float4 acc = make_float4(0.f, 0.f, 0.f, 0.f);

    if (deg <= 32) {
        bool valid = lane < deg;
        int s = 0;
        float4 ee = make_float4(0.f, 0.f, 0.f, 0.f);
        if (valid) {
            s = g_csr_src[off + lane];
            float4 a = *(const float4*)(g_el1 + (size_t)s * 4);
            ee.x = __expf(lrelu(a.x + erd.x));
            ee.y = __expf(lrelu(a.y + erd.y));
            ee.z = __expf(lrelu(a.z + erd.z));
            ee.w = __expf(lrelu(a.w + erd.w));
        }
        float4 sm = ee;
#pragma unroll
        for (int o = 16; o; o >>= 1) {
            sm.x += __shfl_xor_sync(0xffffffffu, sm.x, o);
            sm.y += __shfl_xor_sync(0xffffffffu, sm.y, o);
            sm.z += __shfl_xor_sync(0xffffffffu, sm.z, o);
            sm.w += __shfl_xor_sync(0xffffffffu, sm.w, o);
        }
        float4 al4 = make_float4(0.f, 0.f, 0.f, 0.f);
        if (valid) {
            al4.x = ee.x / sm.x; al4.y = ee.y / sm.y;
            al4.z = ee.z / sm.z; al4.w = ee.w / sm.w;
        }
        s_src[w][lane] = s;
        *(float4*)(&s_alpha[w][lane][0]) = al4;
        __syncwarp();

        for (int q = 0; q < deg; q++) {
            int   sq = s_src[w][q];
            float a  = s_alpha[w][q][head];
            uint2 raw = *(const uint2*)(g_h1h + (size_t)sq * HID + lane * 4);
            float2 f0 = __half22float2(*reinterpret_cast<__half2*>(&raw.x));
            float2 f1 = __half22float2(*reinterpret_cast<__half2*>(&raw.y));
            acc.x += a * f0.x; acc.y += a * f0.y;
            acc.z += a * f1.x; acc.w += a * f1.y;
        }
    } else {
        float4 sm = make_float4(0.f, 0.f, 0.f, 0.f);
        for (int base = 0; base < deg; base += 32) {
            int j = base + lane;
            if (j < deg) {
                int s = g_csr_src[off + j];
                float4 a = *(const float4*)(g_el1 + (size_t)s * 4);
                float4 e4;
                e4.x = __expf(lrelu(a.x + erd.x));
                e4.y = __expf(lrelu(a.y + erd.y));
                e4.z = __expf(lrelu(a.z + erd.z));
                e4.w = __expf(lrelu(a.w + erd.w));
                *(float4*)(g_e1 + (size_t)(off + j) * 4) = e4;
                sm.x += e4.x; sm.y += e4.y; sm.z += e4.z; sm.w += e4.w;
            }
        }
#pragma unroll
        for (int o = 16; o; o >>= 1) {
            sm.x += __shfl_xor_sync(0xffffffffu, sm.x, o);
            sm.y += __shfl_xor_sync(0xffffffffu, sm.y, o);
            sm.z += __shfl_xor_sync(0xffffffffu, sm.z, o);
            sm.w += __shfl_xor_sync(0xffffffffu, sm.w, o);
        }
        float invh = 1.f / ((head == 0) ? sm.x : (head == 1) ? sm.y : (head == 2) ? sm.z : sm.w);

        for (int base = 0; base < deg; base += 32) {
            int cnt = min(32, deg - base);
            int j = base + lane;
            int s = 0;
            float4 ee = make_float4(0.f, 0.f, 0.f, 0.f);
            if (j < deg) {
                s = g_csr_src[off + j];
                ee = *(const float4*)(g_e1 + (size_t)(off + j) * 4);
            }
            s_src[w][lane] = s;
            *(float4*)(&s_alpha[w][lane][0]) = ee;
            __syncwarp();
            for (int q = 0; q < cnt; q++) {
                int   sq = s_src[w][q];
                float a  = s_alpha[w][q][head] * invh;
                uint2 raw = *(const uint2*)(g_h1h + (size_t)sq * HID + lane * 4);
                float2 f0 = __half22float2(*reinterpret_cast<__half2*>(&raw.x));
                float2 f1 = __half22float2(*reinterpret_cast<__half2*>(&raw.y));
                acc.x += a * f0.x; acc.y += a * f0.y;
                acc.z += a * f1.x; acc.w += a * f1.y;
            }
            __syncwarp();
        }
    }

    float4 bb = *(const float4*)(b1 + lane * 4);
    float4 o;
    o.x = elu(acc.x + bb.x); o.y = elu(acc.y + bb.y);
    o.z = elu(acc.z + bb.z); o.w = elu(acc.w + bb.w);
    *(float4*)(g_out1 + (size_t)node * HID + lane * 4) = o;
}

// ============================================================================
// Layer 2: warp per node (1 head, C=40); no max pass; simple gather
// ============================================================================
__global__ __launch_bounds__(256)
void gat2_kernel(float* __restrict__ out, const float* __restrict__ b2, int n)
{
    __shared__ float s_a[8][32];
    __shared__ int   s_src[8][32];

    int w    = threadIdx.x >> 5;
    int node = (blockIdx.x * blockDim.x + threadIdx.x) >> 5;
    int lane = threadIdx.x & 31;
    if (node >= n) return;

    int off = g_off[node];
    int deg = g_off[node + 1] - off;
    float erd = g_er2[node];

    float acc0 = 0.f, acc1 = 0.f;

    if (deg <= 32) {
        bool valid = lane < deg;
        int s = 0;
        float ee = 0.f;
        if (valid) {
            s = g_csr_src[off + lane];
            ee = __expf(lrelu(g_el2[s] + erd));
        }
        float sm = ee;
#pragma unroll
        for (int o = 16; o; o >>= 1)
            sm += __shfl_xor_sync(0xffffffffu, sm, o);
        float alpha = valid ? (ee / sm) : 0.f;

        s_src[w][lane] = s;
        s_a[w][lane] = alpha;
        __syncwarp();

        for (int q = 0; q < deg; q++) {
            int   sq = s_src[w][q];
            float a  = s_a[w][q];
            const float* hp = g_h2 + (size_t)sq * C2;
            acc0 += a * hp[lane];
            if (lane < 8) acc1 += a * hp[32 + lane];
        }
    } else {
        float sm = 0.f;
        for (int base = 0; base < deg; base += 32) {
            int j = base + lane;
            if (j < deg) {
                int s = g_csr_src[off + j];
                float ee = __expf(lrelu(g_el2[s] + erd));
                g_e2[off + j] = ee;
                sm += ee;
            }
        }
#pragma unroll
        for (int o = 16; o; o >>= 1)
            sm += __shfl_xor_sync(0xffffffffu, sm, o);
        float inv = 1.f / sm;

        for (int base = 0; base < deg; base += 32) {
            int cnt = min(32, deg - base);
            int j = base + lane;
            int s = 0; float ee = 0.f;
            if (j < deg) {
                s = g_csr_src[off + j];
                ee = g_e2[off + j];
            }
            s_src[w][lane] = s;
            s_a[w][lane] = ee * inv;
            __syncwarp();
            for (int q = 0; q < cnt; q++) {
                int   sq = s_src[w][q];
                float a  = s_a[w][q];
                const float* hp = g_h2 + (size_t)sq * C2;
                acc0 += a * hp[lane];
                if (lane < 8) acc1 += a * hp[32 + lane];
            }
            __syncwarp();
        }
    }

    out[(size_t)node * C2 + lane] = acc0 + b2[lane];
    if (lane < 8)
        out[(size_t)node * C2 + 32 + lane] = acc1 + b2[32 + lane];
}

// ============================================================================
// launch — CSR ∥ gemm1 fork (gemm1 = submission #4, ncu target), then serial
// ============================================================================
extern "C" void kernel_launch(void* const* d_in, const int* in_sizes, int n_in,
                              void* d_out, int out_size)
{
    const float* feat = (const float*)d_in[0];
    const int*   src  = (const int*)  d_in[1];
    const int*   dst  = (const int*)  d_in[2];
    const float* W1   = (const float*)d_in[3];
    const float* al1  = (const float*)d_in[4];
    const float* ar1  = (const float*)d_in[5];
    const float* b1   = (const float*)d_in[6];
    const float* W2   = (const float*)d_in[7];
    const float* al2  = (const float*)d_in[8];
    const float* ar2  = (const float*)d_in[9];
    const float* b2   = (const float*)d_in[10];
    float* out = (float*)d_out;

    const int n = in_sizes[0] / INDIM;   // 100000
    const int e = in_sizes[1];           // 1600000

    __half* p_h1h = 0;
    float *p_out1 = 0, *p_h2 = 0;
    cudaGetSymbolAddress((void**)&p_h1h,  g_h1h);
    cudaGetSymbolAddress((void**)&p_out1, g_out1);
    cudaGetSymbolAddress((void**)&p_h2,   g_h2);

    static cudaStream_t s2 = 0;
    static cudaEvent_t ev_fork = 0, ev_join = 0;
    if (!s2) {
        cudaStreamCreateWithFlags(&s2, cudaStreamNonBlocking);
        cudaEventCreateWithFlags(&ev_fork, cudaEventDisableTiming);
        cudaEventCreateWithFlags(&ev_join, cudaEventDisableTiming);
    }

    const int TB = 256;
    const int nblk_scan = (n + 1023) / 1024;

    // fork
    cudaEventRecord(ev_fork, 0);
    cudaStreamWaitEvent(s2, ev_fork, 0);

    // s2: first 3 CSR kernels (#1-3)
    zero_deg<<<(n + TB - 1) / TB, TB, 0, s2>>>(n);
    count_kernel<<<(e + TB - 1) / TB, TB, 0, s2>>>(dst, e);
    scan_local<<<nblk_scan, 1024, 0, s2>>>(n);

    // stream 0: gemm1 TF32 (#4 — ncu target)
    gemm1_tc<<<(n + 127) / 128, 256>>>(feat, W1, p_h1h, al1, ar1, n);

    // s2: rest of CSR
    scan_part<<<1, 32, 0, s2>>>(nblk_scan, n);
    add_part<<<(n + TB - 1) / TB, TB, 0, s2>>>(n);
    scatter_kernel<<<(e + TB - 1) / TB, TB, 0, s2>>>(src, dst, e);
    cudaEventRecord(ev_join, s2);

    // join, then serial: gat1 -> gemm2 (TF32) -> gat2
    cudaStreamWaitEvent(0, ev_join, 0);
    gat1_kernel<<<(n * 32 + TB - 1) / TB, TB>>>(b1, n);
    gemm2_tc<<<(n + 127) / 128, 256>>>(p_out1, W2, p_h2, al2, ar2, n);
    gat2_kernel<<<(n * 32 + TB - 1) / TB, TB>>>(out, b2, n);
}

// round 16
// speedup vs baseline: 1.1702x; 1.0256x over previous
#include <cuda_runtime.h>
#include <cuda_fp16.h>

// Problem constants (fixed by the dataset)
#define INDIM 256
#define HID   128     // H * F1
#define NH    4
#define FD    32
#define C2    40      // classes
#define NMAXN 100000
#define EMAXE 1600000

// -------- scratch (static device globals; no allocations anywhere) --------
__device__ __half g_h1h [(size_t)NMAXN * HID];   // layer1 projection (fp16)
__device__ __half g_out1h[(size_t)NMAXN * HID];  // layer1 output (fp16; TF32-exact)
__device__ __half g_h2h [(size_t)NMAXN * C2];    // layer2 projection (fp16)
__device__ float g_el1 [NMAXN * NH];
__device__ float g_er1 [NMAXN * NH];
__device__ float g_el2 [NMAXN];
__device__ float g_er2 [NMAXN];
__device__ float g_e1  [(size_t)EMAXE * NH];    // slow-path scratch only
__device__ float g_e2  [EMAXE];                 // slow-path scratch only
// CSR by dst
__device__ int   g_deg [NMAXN];
__device__ int   g_off [NMAXN + 1];
__device__ int   g_cur [NMAXN];
__device__ int   g_part[256];
__device__ int   g_csr_src[EMAXE];

// -------- helpers --------
__device__ __forceinline__ float lrelu(float v) { return v > 0.f ? v : 0.2f * v; }
__device__ __forceinline__ float elu(float v)   { return v > 0.f ? v : (__expf(v) - 1.f); }

__device__ __forceinline__ unsigned int f2tf32(float f) {
    unsigned int u; asm("cvt.rna.tf32.f32 %0, %1;" : "=r"(u) : "f"(f)); return u;
}

#define MMA_TF32(d, a, b) \
    asm volatile("mma.sync.aligned.m16n8k8.row.col.f32.tf32.tf32.f32 " \
        "{%0,%1,%2,%3}, {%4,%5,%6,%7}, {%8,%9}, {%0,%1,%2,%3};" \
        : "+f"((d)[0]), "+f"((d)[1]), "+f"((d)[2]), "+f"((d)[3]) \
        : "r"((a)[0]), "r"((a)[1]), "r"((a)[2]), "r"((a)[3]), \
          "r"((b)[0]), "r"((b)[1]))

// ============================================================================
// GEMM1 (TF32) + fused elr1 — validated; h1 stored fp16.
// ============================================================================
__global__ __launch_bounds__(256)
void gemm1_tc(const float* __restrict__ A, const float* __restrict__ W,
              __half* __restrict__ H,
              const float* __restrict__ al, const float* __restrict__ ar,
              int nrows)
{
    __shared__ unsigned int As[128][36];
    __shared__ unsigned int Ws[32][136];
    __shared__ float sel[128][4], ser[128][4];

    const int tid  = threadIdx.x;
    const int wid  = tid >> 5;
    const int lane = tid & 31;
    const int wr   = wid >> 1;
    const int wc   = wid & 1;
    const int r0   = blockIdx.x * 128;
    const int qr   = lane >> 2;
    const int qc   = lane & 3;

    float acc[2][8][4];
#pragma unroll
    for (int mt = 0; mt < 2; mt++)
#pragma unroll
        for (int nt = 0; nt < 8; nt++)
#pragma unroll
            for (int j = 0; j < 4; j++) acc[mt][nt][j] = 0.f;

    for (int kt = 0; kt < INDIM; kt += 32) {
#pragma unroll
        for (int i = 0; i < 4; i++) {
            int idx = tid + i * 256;
            int row = idx >> 3;
            int q   = (idx & 7) * 4;
            float4 v = make_float4(0.f, 0.f, 0.f, 0.f);
            if (r0 + row < nrows)
                v = *(const float4*)(A + (size_t)(r0 + row) * INDIM + kt + q);
            As[row][q + 0] = f2tf32(v.x); As[row][q + 1] = f2tf32(v.y);
            As[row][q + 2] = f2tf32(v.z); As[row][q + 3] = f2tf32(v.w);
        }
#pragma unroll
        for (int i = 0; i < 4; i++) {
            int idx = tid + i * 256;
            int kr  = idx >> 5;
            int cq  = (idx & 31) * 4;
            float4 v = *(const float4*)(W + (size_t)(kt + kr) * 128 + cq);
            Ws[kr][cq + 0] = f2tf32(v.x); Ws[kr][cq + 1] = f2tf32(v.y);
            Ws[kr][cq + 2] = f2tf32(v.z); Ws[kr][cq + 3] = f2tf32(v.w);
        }
        __syncthreads();

#pragma unroll
        for (int kc = 0; kc < 4; kc++) {
            const int k0 = kc * 8;
            unsigned int a[2][4], b[8][2];
#pragma unroll
            for (int mt = 0; mt < 2; mt++) {
                int row = wr * 32 + mt * 16 + qr;
                a[mt][0] = As[row    ][k0 + qc];
                a[mt][1] = As[row + 8][k0 + qc];
                a[mt][2] = As[row    ][k0 + qc + 4];
                a[mt][3] = As[row + 8][k0 + qc + 4];
            }
#pragma unroll
            for (int nt = 0; nt < 8; nt++) {
                int col = wc * 64 + nt * 8 + qr;
                b[nt][0] = Ws[k0 + qc    ][col];
                b[nt][1] = Ws[k0 + qc + 4][col];
            }
#pragma unroll
            for (int mt = 0; mt < 2; mt++)
#pragma unroll
                for (int nt = 0; nt < 8; nt++)
                    MMA_TF32(acc[mt][nt], a[mt], b[nt]);
        }
        __syncthreads();
    }

    if (tid < 128) {
        *(float4*)(&sel[tid][0]) = make_float4(0.f, 0.f, 0.f, 0.f);
        *(float4*)(&ser[tid][0]) = make_float4(0.f, 0.f, 0.f, 0.f);
    }
    __syncthreads();

#pragma unroll
    for (int mt = 0; mt < 2; mt++) {
#pragma unroll
        for (int half = 0; half < 2; half++) {
            int lrow = wr * 32 + mt * 16 + qr + half * 8;
            int grow = r0 + lrow;
            bool ok = grow < nrows;
            float pel[2] = {0.f, 0.f}, per[2] = {0.f, 0.f};
#pragma unroll
            for (int nt = 0; nt < 8; nt++) {
                float v0 = acc[mt][nt][half * 2 + 0];
                float v1 = acc[mt][nt][half * 2 + 1];
                int col0 = wc * 64 + nt * 8 + qc * 2;
                if (ok) {
                    __half2 p = __floats2half2_rn(v0, v1);
                    *(__half2*)(H + (size_t)grow * 128 + col0) = p;
                }
                int h = nt >> 2;
                pel[h] += v0 * al[col0] + v1 * al[col0 + 1];
                per[h] += v0 * ar[col0] + v1 * ar[col0 + 1];
            }
            atomicAdd(&sel[lrow][2 * wc + 0], pel[0]);
            atomicAdd(&sel[lrow][2 * wc + 1], pel[1]);
            atomicAdd(&ser[lrow][2 * wc + 0], per[0]);
            atomicAdd(&ser[lrow][2 * wc + 1], per[1]);
        }
    }
    __syncthreads();

    if (tid < 128 && r0 + tid < nrows) {
        *(float4*)(g_el1 + (size_t)(r0 + tid) * 4) = *(float4*)(&sel[tid][0]);
        *(float4*)(g_er1 + (size_t)(r0 + tid) * 4) = *(float4*)(&ser[tid][0]);
    }
}

// ============================================================================
// GEMM2 (TF32) + fused elr2 — A read from fp16 out1 (TF32-exact), h2 out fp16
// ============================================================================
__global__ __launch_bounds__(256)
void gemm2_tc(const __half* __restrict__ A, const float* __restrict__ W2,
              __half* __restrict__ H2,
              const float* __restrict__ al, const float* __restrict__ ar,
              int nrows)
{
    __shared__ unsigned int As[128][36];
    __shared__ unsigned int Ws[32][72];
    __shared__ float sel[128], ser[128];

    const int tid  = threadIdx.x;
    const int wid  = tid >> 5;
    const int lane = tid & 31;
    const int wr   = wid >> 1;
    const int wc   = wid & 1;
    const int r0   = blockIdx.x * 128;
    const int qr   = lane >> 2;
    const int qc   = lane & 3;

    float acc[2][4][4];
#pragma unroll
    for (int mt = 0; mt < 2; mt++)
#pragma unroll
        for (int nt = 0; nt < 4; nt++)
#pragma unroll
            for (int j = 0; j < 4; j++) acc[mt][nt][j] = 0.f;

    for (int kt = 0; kt < HID; kt += 32) {
#pragma unroll
        for (int i = 0; i < 4; i++) {
            int idx = tid + i * 256;
            int row = idx >> 3;
            int q   = (idx & 7) * 4;
            float2 f0 = make_float2(0.f, 0.f), f1 = make_float2(0.f, 0.f);
            if (r0 + row < nrows) {
                uint2 raw = *(const uint2*)(A + (size_t)(r0 + row) * HID + kt + q);
                f0 = __half22float2(*reinterpret_cast<__half2*>(&raw.x));
                f1 = __half22float2(*reinterpret_cast<__half2*>(&raw.y));
            }
            As[row][q + 0] = f2tf32(f0.x); As[row][q + 1] = f2tf32(f0.y);
            As[row][q + 2] = f2tf32(f1.x); As[row][q + 3] = f2tf32(f1.y);
        }
#pragma unroll
        for (int i = 0; i < 2; i++) {
            int idx = tid + i * 256;
            int kr  = idx >> 4;
            int cq  = (idx & 15) * 4;
            float4 v = make_float4(0.f, 0.f, 0.f, 0.f);
            if (cq < C2)
                v = *(const float4*)(W2 + (size_t)(kt + kr) * C2 + cq);
            Ws[kr][cq + 0] = f2tf32(v.x); Ws[kr][cq + 1] = f2tf32(v.y);
            Ws[kr][cq + 2] = f2tf32(v.z); Ws[kr][cq + 3] = f2tf32(v.w);
        }
        __syncthreads();

#pragma unroll
        for (int kc = 0; kc < 4; kc++) {
            const int k0 = kc * 8;
            unsigned int a[2][4], b[4][2];
#pragma unroll
            for (int mt = 0; mt < 2; mt++) {
                int row = wr * 32 + mt * 16 + qr;
                a[mt][0] = As[row    ][k0 + qc];
                a[mt][1] = As[row + 8][k0 + qc];
                a[mt][2] = As[row    ][k0 + qc + 4];
                a[mt][3] = As[row + 8][k0 + qc + 4];
            }
#pragma unroll
            for (int nt = 0; nt < 4; nt++) {
                int col = wc * 32 + nt * 8 + qr;
                b[nt][0] = Ws[k0 + qc    ][col];
                b[nt][1] = Ws[k0 + qc + 4][col];
            }
#pragma unroll
            for (int mt = 0; mt < 2; mt++)
#pragma unroll
                for (int nt = 0; nt < 4; nt++)
                    MMA_TF32(acc[mt][nt], a[mt], b[nt]);
        }
        __syncthreads();
    }

    if (tid < 128) { sel[tid] = 0.f; ser[tid] = 0.f; }
    __syncthreads();

#pragma unroll
    for (int mt = 0; mt < 2; mt++) {
#pragma unroll
        for (int half = 0; half < 2; half++) {
            int lrow = wr * 32 + mt * 16 + qr + half * 8;
            int grow = r0 + lrow;
            bool ok = grow < nrows;
            float pel = 0.f, per = 0.f;
#pragma unroll
            for (int nt = 0; nt < 4; nt++) {
                float v0 = acc[mt][nt][half * 2 + 0];
                float v1 = acc[mt][nt][half * 2 + 1];
                int col0 = wc * 32 + nt * 8 + qc * 2;
                if (col0 < C2) {
                    if (ok) {
                        __half2 p = __floats2half2_rn(v0, v1);
                        *(__half2*)(H2 + (size_t)grow * C2 + col0) = p;
                    }
                    pel += v0 * al[col0] + v1 * al[col0 + 1];
                    per += v0 * ar[col0] + v1 * ar[col0 + 1];
                }
            }
            atomicAdd(&sel[lrow], pel);
            atomicAdd(&ser[lrow], per);
        }
    }
    __syncthreads();

    if (tid < 128 && r0 + tid < nrows) {
        g_el2[r0 + tid] = sel[tid];
        g_er2[r0 + tid] = ser[tid];
    }
}

// ============================================================================
// CSR build
// ============================================================================
__global__ void zero_deg(int n)
{
    int i = blockIdx.x * blockDim.x + threadIdx.x;
    if (i < n) g_deg[i] = 0;
}

__global__ void count_kernel(const int* __restrict__ dst, int e)
{
    int i = blockIdx.x * blockDim.x + threadIdx.x;
    if (i < e) atomicAdd(&g_deg[dst[i]], 1);
}

__global__ __launch_bounds__(1024)
void scan_local(int n)
{
    __shared__ int sh[1024];
    int t = threadIdx.x;
    int i = blockIdx.x * 1024 + t;
    int val = (i < n) ? g_deg[i] : 0;
    sh[t] = val;
    __syncthreads();
#pragma unroll
    for (int d = 1; d < 1024; d <<= 1) {
        int x = (t >= d) ? sh[t - d] : 0;
        __syncthreads();
        sh[t] += x;
        __syncthreads();
    }
    if (i < n) g_off[i] = sh[t] - val;
    if (t == 1023) g_part[blockIdx.x] = sh[1023];
}

__global__ void scan_part(int nblk, int n)
{
    if (threadIdx.x != 0 || blockIdx.x != 0) return;
    int run = 0;
    for (int b = 0; b < nblk; b++) {
        int v = g_part[b];
        g_part[b] = run;
        run += v;
    }
    g_off[n] = run;
}

__global__ void add_part(int n)
{
    int i = blockIdx.x * blockDim.x + threadIdx.x;
    if (i >= n) return;
    int o = g_off[i] + g_part[i >> 10];
    g_off[i] = o;
    g_cur[i] = o;
}

__global__ void scatter_kernel(const int* __restrict__ src, const int* __restrict__ dst, int e)
{
    int i = blockIdx.x * blockDim.x + threadIdx.x;
    if (i >= e) return;
    int d = dst[i];
    int pos = atomicAdd(&g_cur[d], 1);
    g_csr_src[pos] = src[i];
}

// ============================================================================
// Layer 1: warp per node — register softmax, fp16 h1 gather, fp16 out1 store
// ============================================================================
__global__ __launch_bounds__(256)
void gat1_kernel(const float* __restrict__ b1, int n)
{
    __shared__ float s_alpha[8][32][4];
    __shared__ int   s_src[8][32];

    int w    = threadIdx.x >> 5;
    int node = (blockIdx.x * blockDim.x + threadIdx.x) >> 5;
    int lane = threadIdx.x & 31;
    if (node >= n) return;

    int off = g_off[node];
    int deg = g_off[node + 1] - off;
    int head = lane >> 3;

    float4 erd = *(const float4*)(g_er1 + (size_t)node * 4);
    float4 acc = make_float4(0.f, 0.f, 0.f, 0.f);

    if (deg <= 32) {
        bool valid = lane < deg;
        int s = 0;
        float4 ee = make_float4(0.f, 0.f, 0.f, 0.f);
        if (valid) {
            s = g_csr_src[off + lane];
            float4 a = *(const float4*)(g_el1 + (size_t)s * 4);
            ee.x = __expf(lrelu(a.x + erd.x));
            ee.y = __expf(lrelu(a.y + erd.y));
            ee.z = __expf(lrelu(a.z + erd.z));
            ee.w = __expf(lrelu(a.w + erd.w));
        }
        float4 sm = ee;
#pragma unroll
        for (int o = 16; o; o >>= 1) {
            sm.x += __shfl_xor_sync(0xffffffffu, sm.x, o);
            sm.y += __shfl_xor_sync(0xffffffffu, sm.y, o);
            sm.z += __shfl_xor_sync(0xffffffffu, sm.z, o);
            sm.w += __shfl_xor_sync(0xffffffffu, sm.w, o);
        }
        float4 al4 = make_float4(0.f, 0.f, 0.f, 0.f);
        if (valid) {
            al4.x = ee.x / sm.x; al4.y = ee.y / sm.y;
            al4.z = ee.z / sm.z; al4.w = ee.w / sm.w;
        }
        s_src[w][lane] = s;
        *(float4*)(&s_alpha[w][lane][0]) = al4;
        __syncwarp();

        for (int q = 0; q < deg; q++) {
            int   sq = s_src[w][q];
            float a  = s_alpha[w][q][head];
            uint2 raw = *(const uint2*)(g_h1h + (size_t)sq * HID + lane * 4);
            float2 f0 = __half22float2(*reinterpret_cast<__half2*>(&raw.x));
            float2 f1 = __half22float2(*reinterpret_cast<__half2*>(&raw.y));
            acc.x += a * f0.x; acc.y += a * f0.y;
            acc.z += a * f1.x; acc.w += a * f1.y;
        }
    } else {
        float4 sm = make_float4(0.f, 0.f, 0.f, 0.f);
        for (int base = 0; base < deg; base += 32) {
            int j = base + lane;
            if (j < deg) {
                int s = g_csr_src[off + j];
                float4 a = *(const float4*)(g_el1 + (size_t)s * 4);
                float4 e4;
                e4.x = __expf(lrelu(a.x + erd.x));
                e4.y = __expf(lrelu(a.y + erd.y));
                e4.z = __expf(lrelu(a.z + erd.z));
                e4.w = __expf(lrelu(a.w + erd.w));
                *(float4*)(g_e1 + (size_t)(off + j) * 4) = e4;
                sm.x += e4.x; sm.y += e4.y; sm.z += e4.z; sm.w += e4.w;
            }
        }
#pragma unroll
        for (int o = 16; o; o >>= 1) {
            sm.x += __shfl_xor_sync(0xffffffffu, sm.x, o);
            sm.y += __shfl_xor_sync(0xffffffffu, sm.y, o);
            sm.z += __shfl_xor_sync(0xffffffffu, sm.z, o);
            sm.w += __shfl_xor_sync(0xffffffffu, sm.w, o);
        }
        float invh = 1.f / ((head == 0) ? sm.x : (head == 1) ? sm.y : (head == 2) ? sm.z : sm.w);

        for (int base = 0; base < deg; base += 32) {
            int cnt = min(32, deg - base);
            int j = base + lane;
            int s = 0;
            float4 ee = make_float4(0.f, 0.f, 0.f, 0.f);
            if (j < deg) {
                s = g_csr_src[off + j];
                ee = *(const float4*)(g_e1 + (size_t)(off + j) * 4);
            }
            s_src[w][lane] = s;
            *(float4*)(&s_alpha[w][lane][0]) = ee;
            __syncwarp();
            for (int q = 0; q < cnt; q++) {
                int   sq = s_src[w][q];
                float a  = s_alpha[w][q][head] * invh;
                uint2 raw = *(const uint2*)(g_h1h + (size_t)sq * HID + lane * 4);
                float2 f0 = __half22float2(*reinterpret_cast<__half2*>(&raw.x));
                float2 f1 = __half22float2(*reinterpret_cast<__half2*>(&raw.y));
                acc.x += a * f0.x; acc.y += a * f0.y;
                acc.z += a * f1.x; acc.w += a * f1.y;
            }
            __syncwarp();
        }
    }

    float4 bb = *(const float4*)(b1 + lane * 4);
    uint2 packed;
    __half2 p0 = __floats2half2_rn(elu(acc.x + bb.x), elu(acc.y + bb.y));
    __half2 p1 = __floats2half2_rn(elu(acc.z + bb.z), elu(acc.w + bb.w));
    packed.x = *reinterpret_cast<unsigned int*>(&p0);
    packed.y = *reinterpret_cast<unsigned int*>(&p1);
    *(uint2*)(g_out1h + (size_t)node * HID + lane * 4) = packed;
}

// ============================================================================
// Layer 2: warp per node (1 head, C=40); fp16 h2 gather
// ============================================================================
__global__ __launch_bounds__(256)
void gat2_kernel(float* __restrict__ out, const float* __restrict__ b2, int n)
{
    __shared__ float s_a[8][32];
    __shared__ int   s_src[8][32];

    int w    = threadIdx.x >> 5;
    int node = (blockIdx.x * blockDim.x + threadIdx.x) >> 5;
    int lane = threadIdx.x & 31;
    if (node >= n) return;

    int off = g_off[node];
    int deg = g_off[node + 1] - off;
    float erd = g_er2[node];

    float acc0 = 0.f, acc1 = 0.f;

    if (deg <= 32) {
        bool valid = lane < deg;
        int s = 0;
        float ee = 0.f;
        if (valid) {
            s = g_csr_src[off + lane];
            ee = __expf(lrelu(g_el2[s] + erd));
        }
        float sm = ee;
#pragma unroll
        for (int o = 16; o; o >>= 1)
            sm += __shfl_xor_sync(0xffffffffu, sm, o);
        float alpha = valid ? (ee / sm) : 0.f;

        s_src[w][lane] = s;
        s_a[w][lane] = alpha;
        __syncwarp();

        for (int q = 0; q < deg; q++) {
            int   sq = s_src[w][q];
            float a  = s_a[w][q];
            const __half* hp = g_h2h + (size_t)sq * C2;
            acc0 += a * __half2float(hp[lane]);
            if (lane < 8) acc1 += a * __half2float(hp[32 + lane]);
        }
    } else {
        float sm = 0.f;
        for (int base = 0; base < deg; base += 32) {
            int j = base + lane;
            if (j < deg) {
                int s = g_csr_src[off + j];
                float ee = __expf(lrelu(g_el2[s] + erd));
                g_e2[off + j] = ee;
                sm += ee;
            }
        }
#pragma unroll
        for (int o = 16; o; o >>= 1)
            sm += __shfl_xor_sync(0xffffffffu, sm, o);
        float inv = 1.f / sm;

        for (int base = 0; base < deg; base += 32) {
            int cnt = min(32, deg - base);
            int j = base + lane;
            int s = 0; float ee = 0.f;
            if (j < deg) {
                s = g_csr_src[off + j];
                ee = g_e2[off + j];
            }
            s_src[w][lane] = s;
            s_a[w][lane] = ee * inv;
            __syncwarp();
            for (int q = 0; q < cnt; q++) {
                int   sq = s_src[w][q];
                float a  = s_a[w][q];
                const __half* hp = g_h2h + (size_t)sq * C2;
                acc0 += a * __half2float(hp[lane]);
                if (lane < 8) acc1 += a * __half2float(hp[32 + lane]);
            }
            __syncwarp();
        }
    }

    out[(size_t)node * C2 + lane] = acc0 + b2[lane];
    if (lane < 8)
        out[(size_t)node * C2 + 32 + lane] = acc1 + b2[32 + lane];
}

// ============================================================================
// launch — CSR ∥ gemm1 fork (gemm1 = submission #4, ncu target), then serial
// ============================================================================
extern "C" void kernel_launch(void* const* d_in, const int* in_sizes, int n_in,
                              void* d_out, int out_size)
{
    const float* feat = (const float*)d_in[0];
    const int*   src  = (const int*)  d_in[1];
    const int*   dst  = (const int*)  d_in[2];
    const float* W1   = (const float*)d_in[3];
    const float* al1  = (const float*)d_in[4];
    const float* ar1  = (const float*)d_in[5];
    const float* b1   = (const float*)d_in[6];
    const float* W2   = (const float*)d_in[7];
    const float* al2  = (const float*)d_in[8];
    const float* ar2  = (const float*)d_in[9];
    const float* b2   = (const float*)d_in[10];
    float* out = (float*)d_out;

    const int n = in_sizes[0] / INDIM;   // 100000
    const int e = in_sizes[1];           // 1600000

    __half *p_h1h = 0, *p_out1h = 0, *p_h2h = 0;
    cudaGetSymbolAddress((void**)&p_h1h,   g_h1h);
    cudaGetSymbolAddress((void**)&p_out1h, g_out1h);
    cudaGetSymbolAddress((void**)&p_h2h,   g_h2h);

    static cudaStream_t s2 = 0;
    static cudaEvent_t ev_fork = 0, ev_join = 0;
    if (!s2) {
        cudaStreamCreateWithFlags(&s2, cudaStreamNonBlocking);
        cudaEventCreateWithFlags(&ev_fork, cudaEventDisableTiming);
        cudaEventCreateWithFlags(&ev_join, cudaEventDisableTiming);
    }

    const int TB = 256;
    const int nblk_scan = (n + 1023) / 1024;

    // fork
    cudaEventRecord(ev_fork, 0);
    cudaStreamWaitEvent(s2, ev_fork, 0);

    // s2: first 3 CSR kernels (#1-3)
    zero_deg<<<(n + TB - 1) / TB, TB, 0, s2>>>(n);
    count_kernel<<<(e + TB - 1) / TB, TB, 0, s2>>>(dst, e);
    scan_local<<<nblk_scan, 1024, 0, s2>>>(n);

    // stream 0: gemm1 TF32 (#4 — ncu target)
    gemm1_tc<<<(n + 127) / 128, 256>>>(feat, W1, p_h1h, al1, ar1, n);

    // s2: rest of CSR
    scan_part<<<1, 32, 0, s2>>>(nblk_scan, n);
    add_part<<<(n + TB - 1) / TB, TB, 0, s2>>>(n);
    scatter_kernel<<<(e + TB - 1) / TB, TB, 0, s2>>>(src, dst, e);
    cudaEventRecord(ev_join, s2);

    // join, then serial: gat1 -> gemm2 (TF32) -> gat2
    cudaStreamWaitEvent(0, ev_join, 0);
    gat1_kernel<<<(n * 32 + TB - 1) / TB, TB>>>(b1, n);
    gemm2_tc<<<(n + 127) / 128, 256>>>(p_out1h, W2, p_h2h, al2, ar2, n);
    gat2_kernel<<<(n * 32 + TB - 1) / TB, TB>>>(out, b2, n);
}